// round 8
// baseline (speedup 1.0000x reference)
#include <cuda_runtime.h>
#include <cuda_bf16.h>
#include <math.h>
#include <stdint.h>

// Problem constants
#define BATCH 4
#define SEQ   2048
#define NH    16
#define DH    64
#define DMODEL 1024
#define M_ROWS (BATCH * SEQ)          // 8192
#define QKV_N  (3 * DMODEL)           // 3072

// Scratch (device globals; allocations are forbidden)
__device__ float g_Q[BATCH * NH * SEQ * DH];    // [b,h,l,d]
__device__ float g_K[BATCH * NH * SEQ * DH];
__device__ float g_V[BATCH * NH * SEQ * DH];
__device__ float g_A[M_ROWS * DMODEL];          // attention output [b,l,h*64+d]
__device__ float g_cos[SEQ * (DH / 2)];
__device__ float g_sin[SEQ * (DH / 2)];

// bf16 split operands for tensor-core GEMMs
__device__ __nv_bfloat16 gx_h[M_ROWS * DMODEL];     // x hi
__device__ __nv_bfloat16 gx_l[M_ROWS * DMODEL];     // x lo
__device__ __nv_bfloat16 ga_h[M_ROWS * DMODEL];     // attn-out hi
__device__ __nv_bfloat16 ga_l[M_ROWS * DMODEL];     // attn-out lo
__device__ __nv_bfloat16 gwq_h[QKV_N * DMODEL];     // W_qkv^T [3072][1024] hi
__device__ __nv_bfloat16 gwq_l[QKV_N * DMODEL];
__device__ __nv_bfloat16 gwp_h[DMODEL * DMODEL];    // W_proj^T [1024][1024] hi
__device__ __nv_bfloat16 gwp_l[DMODEL * DMODEL];

// ---------------------------------------------------------------------------
// RoPE table
// ---------------------------------------------------------------------------
__global__ void rope_table_kernel() {
    int l = blockIdx.x;
    int i = threadIdx.x;
    double inv = pow(10000.0, -(2.0 * (double)i) / (double)DH);
    double ph  = (double)l * inv;
    g_cos[l * 32 + i] = (float)cos(ph);
    g_sin[l * 32 + i] = (float)sin(ph);
}

// ---------------------------------------------------------------------------
// In-place RoPE on Q (which=0) or K (which=1)
// ---------------------------------------------------------------------------
__global__ void rope_apply_kernel(int which) {
    int p = blockIdx.x * blockDim.x + threadIdx.x;
    const int TOTAL = BATCH * NH * SEQ * 32;
    if (p >= TOTAL) return;
    float* T = which ? g_K : g_Q;
    float2* tp = (float2*)T;
    int i = p & 31;
    int l = (p >> 5) & (SEQ - 1);
    float2 v = tp[p];
    float c = g_cos[l * 32 + i];
    float s = g_sin[l * 32 + i];
    float2 r;
    r.x = v.x * c - v.y * s;
    r.y = v.x * s + v.y * c;
    tp[p] = r;
}

// ---------------------------------------------------------------------------
// fp32 -> bf16 hi/lo split (elementwise, same layout)
// ---------------------------------------------------------------------------
__global__ void split_fp32_kernel(const float* __restrict__ src,
                                  __nv_bfloat16* __restrict__ h,
                                  __nv_bfloat16* __restrict__ l, int n) {
    int i = blockIdx.x * blockDim.x + threadIdx.x;
    if (i >= n) return;
    float v = src[i];
    __nv_bfloat16 hh = __float2bfloat16(v);
    h[i] = hh;
    l[i] = __float2bfloat16(v - __bfloat162float(hh));
}

// split of g_A (mode helper; device-global source)
__global__ void split_ga_kernel(int n) {
    int i = blockIdx.x * blockDim.x + threadIdx.x;
    if (i >= n) return;
    float v = g_A[i];
    __nv_bfloat16 hh = __float2bfloat16(v);
    ga_h[i] = hh;
    ga_l[i] = __float2bfloat16(v - __bfloat162float(hh));
}

// ---------------------------------------------------------------------------
// Transpose + split: W [K][N] fp32 -> Th/Tl [N][K] bf16. Tiled via smem.
// Block (32, 8); grid (N/32, K/32).
// ---------------------------------------------------------------------------
__global__ void transpose_split_kernel(const float* __restrict__ W,
                                       __nv_bfloat16* __restrict__ Th,
                                       __nv_bfloat16* __restrict__ Tl,
                                       int K, int N) {
    __shared__ float tile[32][33];
    int n0 = blockIdx.x * 32;
    int k0 = blockIdx.y * 32;
    int tx = threadIdx.x, ty = threadIdx.y;
#pragma unroll
    for (int i = 0; i < 4; i++)
        tile[ty + i * 8][tx] = W[(size_t)(k0 + ty + i * 8) * N + n0 + tx];
    __syncthreads();
#pragma unroll
    for (int i = 0; i < 4; i++) {
        float v = tile[tx][ty + i * 8];
        __nv_bfloat16 hh = __float2bfloat16(v);
        size_t off = (size_t)(n0 + ty + i * 8) * K + k0 + tx;
        Th[off] = hh;
        Tl[off] = __float2bfloat16(v - __bfloat162float(hh));
    }
}

// ---------------------------------------------------------------------------
// bf16x3 split-precision tensor-core GEMM.
// C[M=8192, N] = A[M,K] @ B^T[N,K] + bias, A/B pre-split into hi/lo bf16.
// mode 0: A = gx (x), B = gwq (W_qkv^T, N=3072), scatter into g_Q/g_K/g_V
// mode 1: A = ga (attn out), B = gwp (W_proj^T, N=1024), write Cout
// BM=BN=128, BK=32. 256 threads = 8 warps (4m x 2n); warp tile 32x64.
// mma.sync.m16n8k16 bf16, fp32 accumulate; 3 products (hh, hl, lh).
// ---------------------------------------------------------------------------
__device__ __forceinline__ void mma16816(float* c, const uint32_t* a,
                                         uint32_t b0, uint32_t b1) {
    asm volatile(
        "mma.sync.aligned.m16n8k16.row.col.f32.bf16.bf16.f32 "
        "{%0,%1,%2,%3}, {%4,%5,%6,%7}, {%8,%9}, {%0,%1,%2,%3};"
        : "+f"(c[0]), "+f"(c[1]), "+f"(c[2]), "+f"(c[3])
        : "r"(a[0]), "r"(a[1]), "r"(a[2]), "r"(a[3]), "r"(b0), "r"(b1));
}

#define SMPAD 40   // 32 + 8 bf16 pad -> conflict-free fragment LDS

__global__ void __launch_bounds__(256)
gemm_bf16x3_kernel(const float* __restrict__ bias, float* __restrict__ Cout,
                   int N, int K, int mode) {
    __shared__ __align__(16) __nv_bfloat16 sAh[128][SMPAD];
    __shared__ __align__(16) __nv_bfloat16 sAl[128][SMPAD];
    __shared__ __align__(16) __nv_bfloat16 sBh[128][SMPAD];
    __shared__ __align__(16) __nv_bfloat16 sBl[128][SMPAD];

    const __nv_bfloat16* Ah = mode ? ga_h : gx_h;
    const __nv_bfloat16* Al = mode ? ga_l : gx_l;
    const __nv_bfloat16* Bh = mode ? gwp_h : gwq_h;
    const __nv_bfloat16* Bl = mode ? gwp_l : gwq_l;

    int tid = threadIdx.x;
    int warp = tid >> 5;
    int lane = tid & 31;
    int wm = warp & 3;          // 0..3  (m)
    int wn = warp >> 2;         // 0..1  (n)
    int g  = lane >> 2;         // 0..7
    int tg = lane & 3;          // 0..3

    int m0 = blockIdx.y * 128;
    int n0 = blockIdx.x * 128;

    float acc[2][8][4];
#pragma unroll
    for (int mi = 0; mi < 2; mi++)
#pragma unroll
        for (int ni = 0; ni < 8; ni++)
#pragma unroll
            for (int r = 0; r < 4; r++) acc[mi][ni][r] = 0.0f;

    // global tile load mapping: 512 uint4 slots per matrix (128 rows x 4)
    for (int k0 = 0; k0 < K; k0 += 32) {
#pragma unroll
        for (int s = 0; s < 2; s++) {
            int j = tid + s * 256;
            int row = j >> 2;
            int cq = (j & 3) * 8;
            size_t aoff = (size_t)(m0 + row) * K + k0 + cq;
            size_t boff = (size_t)(n0 + row) * K + k0 + cq;
            *(uint4*)&sAh[row][cq] = *(const uint4*)(Ah + aoff);
            *(uint4*)&sAl[row][cq] = *(const uint4*)(Al + aoff);
            *(uint4*)&sBh[row][cq] = *(const uint4*)(Bh + boff);
            *(uint4*)&sBl[row][cq] = *(const uint4*)(Bl + boff);
        }
        __syncthreads();

#pragma unroll
        for (int ks = 0; ks < 32; ks += 16) {
            uint32_t afh[2][4], afl[2][4];
#pragma unroll
            for (int mi = 0; mi < 2; mi++) {
                int rb = wm * 32 + mi * 16;
                int c0 = ks + tg * 2;
                afh[mi][0] = *(const uint32_t*)&sAh[rb + g][c0];
                afh[mi][1] = *(const uint32_t*)&sAh[rb + g + 8][c0];
                afh[mi][2] = *(const uint32_t*)&sAh[rb + g][c0 + 8];
                afh[mi][3] = *(const uint32_t*)&sAh[rb + g + 8][c0 + 8];
                afl[mi][0] = *(const uint32_t*)&sAl[rb + g][c0];
                afl[mi][1] = *(const uint32_t*)&sAl[rb + g + 8][c0];
                afl[mi][2] = *(const uint32_t*)&sAl[rb + g][c0 + 8];
                afl[mi][3] = *(const uint32_t*)&sAl[rb + g + 8][c0 + 8];
            }
#pragma unroll
            for (int ni = 0; ni < 8; ni++) {
                int nb = wn * 64 + ni * 8;
                int c0 = ks + tg * 2;
                uint32_t bh0 = *(const uint32_t*)&sBh[nb + g][c0];
                uint32_t bh1 = *(const uint32_t*)&sBh[nb + g][c0 + 8];
                uint32_t bl0 = *(const uint32_t*)&sBl[nb + g][c0];
                uint32_t bl1 = *(const uint32_t*)&sBl[nb + g][c0 + 8];
#pragma unroll
                for (int mi = 0; mi < 2; mi++) {
                    mma16816(acc[mi][ni], afh[mi], bh0, bh1);  // Ah*Bh
                    mma16816(acc[mi][ni], afh[mi], bl0, bl1);  // Ah*Bl
                    mma16816(acc[mi][ni], afl[mi], bh0, bh1);  // Al*Bh
                }
            }
        }
        __syncthreads();
    }

    // Epilogue: c0,c1 -> (row g, col tg*2/+1); c2,c3 -> (row g+8, same cols)
#pragma unroll
    for (int mi = 0; mi < 2; mi++) {
#pragma unroll
        for (int ni = 0; ni < 8; ni++) {
            int col = n0 + wn * 64 + ni * 8 + tg * 2;
            float bx = bias[col];
            float by = bias[col + 1];
#pragma unroll
            for (int half = 0; half < 2; half++) {
                int row = m0 + wm * 32 + mi * 16 + g + half * 8;
                float vx = acc[mi][ni][half * 2 + 0] + bx;
                float vy = acc[mi][ni][half * 2 + 1] + by;
                if (mode == 0) {
                    int b = row >> 11;
                    int l = row & (SEQ - 1);
                    int part = col >> 10;         // 0=q,1=k,2=v
                    int rem  = col & 1023;
                    int h    = rem >> 6;
                    int d    = rem & 63;          // even, <=62
                    float* dst = (part == 0) ? g_Q : (part == 1) ? g_K : g_V;
                    size_t off = ((size_t)((b * NH + h) * SEQ + l)) * DH + d;
                    *(float2*)(dst + off) = make_float2(vx, vy);
                } else {
                    *(float2*)(Cout + (size_t)row * N + col) = make_float2(vx, vy);
                }
            }
        }
    }
}

// ---------------------------------------------------------------------------
// Flash attention (causal + key mask), fp32. Unchanged from round 4.
// ---------------------------------------------------------------------------
__global__ void __launch_bounds__(128)
flash_attn_kernel(const int* __restrict__ mask) {
    __shared__ float Ks[64][64];
    __shared__ float Vs[64][64];
    __shared__ int   ms[64];

    int bh = blockIdx.y;
    int b  = bh >> 4;
    int h  = bh & 15;
    int qbase = blockIdx.x * 128;
    int t = threadIdx.x;
    int row = qbase + t;

    const float* qptr = g_Q + ((size_t)bh * SEQ + row) * DH;
    float4 q[16];
#pragma unroll
    for (int i = 0; i < 16; i++) q[i] = *(const float4*)(qptr + i * 4);

    float m = -INFINITY;
    float lsum = 0.0f;
    float4 o[16];
#pragma unroll
    for (int i = 0; i < 16; i++) o[i] = make_float4(0.f, 0.f, 0.f, 0.f);

    const float scale = 0.125f;
    int ntiles = blockIdx.x * 2 + 2;

    for (int tile = 0; tile < ntiles; tile++) {
        int kb = tile * 64;
        const float4* kp = (const float4*)(g_K + ((size_t)bh * SEQ + kb) * DH);
        const float4* vp = (const float4*)(g_V + ((size_t)bh * SEQ + kb) * DH);
#pragma unroll
        for (int i = 0; i < 8; i++) {
            ((float4*)Ks)[t + i * 128] = kp[t + i * 128];
            ((float4*)Vs)[t + i * 128] = vp[t + i * 128];
        }
        if (t < 64) ms[t] = mask[b * SEQ + kb + t];
        __syncthreads();

        int kmax = row - kb + 1;
        if (kmax > 64) kmax = 64;
        for (int kk = 0; kk < kmax; kk++) {
            if (!ms[kk]) continue;
            const float4* kr = (const float4*)&Ks[kk][0];
            float s0 = 0.f, s1 = 0.f, s2 = 0.f, s3 = 0.f;
#pragma unroll
            for (int i = 0; i < 16; i++) {
                float4 kv = kr[i];
                float4 qv = q[i];
                s0 += qv.x * kv.x;
                s1 += qv.y * kv.y;
                s2 += qv.z * kv.z;
                s3 += qv.w * kv.w;
            }
            float s = ((s0 + s1) + (s2 + s3)) * scale;
            if (s > m) {
                float c = __expf(m - s);
                lsum *= c;
#pragma unroll
                for (int i = 0; i < 16; i++) {
                    o[i].x *= c; o[i].y *= c; o[i].z *= c; o[i].w *= c;
                }
                m = s;
            }
            float p = __expf(s - m);
            lsum += p;
            const float4* vr = (const float4*)&Vs[kk][0];
#pragma unroll
            for (int i = 0; i < 16; i++) {
                float4 vv = vr[i];
                o[i].x += p * vv.x;
                o[i].y += p * vv.y;
                o[i].z += p * vv.z;
                o[i].w += p * vv.w;
            }
        }
        __syncthreads();
    }

    float inv = (lsum > 0.f) ? (1.0f / lsum) : 0.f;
    float* op = g_A + ((size_t)(b * SEQ + row)) * DMODEL + h * DH;
#pragma unroll
    for (int i = 0; i < 16; i++) {
        float4 v;
        v.x = o[i].x * inv; v.y = o[i].y * inv;
        v.z = o[i].z * inv; v.w = o[i].w * inv;
        *(float4*)(op + i * 4) = v;
    }
}

// ---------------------------------------------------------------------------
// Launch
// ---------------------------------------------------------------------------
extern "C" void kernel_launch(void* const* d_in, const int* in_sizes, int n_in,
                              void* d_out, int out_size) {
    const float* x      = (const float*)d_in[0];
    const float* W_qkv  = (const float*)d_in[1];
    const float* b_qkv  = (const float*)d_in[2];
    const float* W_proj = (const float*)d_in[3];
    const float* b_proj = (const float*)d_in[4];
    const int*   amask  = (const int*)d_in[5];
    float* out = (float*)d_out;

    // 1. RoPE tables
    rope_table_kernel<<<SEQ, 32>>>();

    // 2. Split/transpose operands for tensor-core GEMMs
    {
        // x -> gx_h/gx_l (requires cudaGetSymbolAddress-free path: kernel refs globals)
        int n = M_ROWS * DMODEL;
        split_fp32_kernel<<<(n + 255) / 256, 256>>>(x, nullptr, nullptr, 0); // no-op guard
    }
    // Direct split of x into gx via dedicated launches (use symbol-referencing kernels)
    {
        int n = M_ROWS * DMODEL;
        // split into gx_h/gx_l: use a small wrapper via transpose-free split
        // (split_fp32_kernel with explicit device-global targets)
        // We fetch addresses with cudaGetSymbolAddress (host query; graph-safe).
        void *ph, *pl;
        cudaGetSymbolAddress(&ph, gx_h);
        cudaGetSymbolAddress(&pl, gx_l);
        split_fp32_kernel<<<(n + 255) / 256, 256>>>(x, (__nv_bfloat16*)ph,
                                                    (__nv_bfloat16*)pl, n);
    }
    {
        void *ph, *pl;
        cudaGetSymbolAddress(&ph, gwq_h);
        cudaGetSymbolAddress(&pl, gwq_l);
        dim3 grid(QKV_N / 32, DMODEL / 32);
        transpose_split_kernel<<<grid, dim3(32, 8)>>>(W_qkv, (__nv_bfloat16*)ph,
                                                      (__nv_bfloat16*)pl, DMODEL, QKV_N);
    }
    {
        void *ph, *pl;
        cudaGetSymbolAddress(&ph, gwp_h);
        cudaGetSymbolAddress(&pl, gwp_l);
        dim3 grid(DMODEL / 32, DMODEL / 32);
        transpose_split_kernel<<<grid, dim3(32, 8)>>>(W_proj, (__nv_bfloat16*)ph,
                                                      (__nv_bfloat16*)pl, DMODEL, DMODEL);
    }

    // 3. QKV GEMM (tensor cores) + scatter to [b,h,l,d]
    {
        dim3 grid(QKV_N / 128, M_ROWS / 128);   // 24 x 64
        gemm_bf16x3_kernel<<<grid, 256>>>(b_qkv, nullptr, QKV_N, DMODEL, 0);
    }

    // 4. RoPE on Q and K
    {
        int total = BATCH * NH * SEQ * 32;
        int blocks = (total + 255) / 256;
        rope_apply_kernel<<<blocks, 256>>>(0);
        rope_apply_kernel<<<blocks, 256>>>(1);
    }

    // 5. Flash attention
    {
        dim3 grid(SEQ / 128, BATCH * NH);       // 16 x 64
        flash_attn_kernel<<<grid, 128>>>(amask);
    }

    // 6. Split attention output, then projection GEMM (tensor cores)
    {
        int n = M_ROWS * DMODEL;
        split_ga_kernel<<<(n + 255) / 256, 256>>>(n);
        dim3 grid(DMODEL / 128, M_ROWS / 128);  // 8 x 64
        gemm_bf16x3_kernel<<<grid, 256>>>(b_proj, out, DMODEL, DMODEL, 1);
    }
}

// round 11
// speedup vs baseline: 1.7320x; 1.7320x over previous
#include <cuda_runtime.h>
#include <cuda_bf16.h>
#include <math.h>
#include <stdint.h>

// Problem constants
#define BATCH 4
#define SEQ   2048
#define NH    16
#define DH    64
#define DMODEL 1024
#define M_ROWS (BATCH * SEQ)          // 8192
#define QKV_N  (3 * DMODEL)           // 3072
#define KK     3072                   // expanded K' = 3 * DMODEL (bf16x3 fold)

// Scratch (device globals; allocations are forbidden)
__device__ float g_Q[BATCH * NH * SEQ * DH];
__device__ float g_K[BATCH * NH * SEQ * DH];
__device__ float g_V[BATCH * NH * SEQ * DH];
__device__ float g_A[M_ROWS * DMODEL];
__device__ float g_cos[SEQ * (DH / 2)];
__device__ float g_sin[SEQ * (DH / 2)];

// Expanded bf16 operands: A' = [Ah | Ah | Al] (rows x 3072),
//                          B' = [Bh | Bl | Bh] (rows x 3072, weights transposed)
__device__ __nv_bfloat16 gxp[M_ROWS * KK];      // x expanded
__device__ __nv_bfloat16 gap[M_ROWS * KK];      // attn-out expanded
__device__ __nv_bfloat16 gwqp[QKV_N * KK];      // W_qkv^T expanded [3072][3072]
__device__ __nv_bfloat16 gwpp[DMODEL * KK];     // W_proj^T expanded [1024][3072]

// ---------------------------------------------------------------------------
// helpers
// ---------------------------------------------------------------------------
__device__ __forceinline__ uint32_t smem_u32(const void* p) {
    uint32_t a;
    asm("{ .reg .u64 t; cvta.to.shared.u64 t, %1; cvt.u32.u64 %0, t; }"
        : "=r"(a) : "l"(p));
    return a;
}

__device__ __forceinline__ void mma16816(float* c, const uint32_t* a,
                                         uint32_t b0, uint32_t b1) {
    asm volatile(
        "mma.sync.aligned.m16n8k16.row.col.f32.bf16.bf16.f32 "
        "{%0,%1,%2,%3}, {%4,%5,%6,%7}, {%8,%9}, {%0,%1,%2,%3};"
        : "+f"(c[0]), "+f"(c[1]), "+f"(c[2]), "+f"(c[3])
        : "r"(a[0]), "r"(a[1]), "r"(a[2]), "r"(a[3]), "r"(b0), "r"(b1));
}

__device__ __forceinline__ void ldmx4(uint32_t* r, uint32_t addr) {
    asm volatile(
        "ldmatrix.sync.aligned.m8n8.x4.shared.b16 {%0,%1,%2,%3}, [%4];"
        : "=r"(r[0]), "=r"(r[1]), "=r"(r[2]), "=r"(r[3]) : "r"(addr));
}

#define CP_ASYNC16(dst, src) \
    asm volatile("cp.async.cg.shared.global [%0], [%1], 16;" \
                 :: "r"(dst), "l"(src) : "memory")
#define CP_COMMIT() asm volatile("cp.async.commit_group;" ::: "memory")
#define CP_WAIT1()  asm volatile("cp.async.wait_group 1;" ::: "memory")

// smem tile: 128 rows x 32 bf16 (64B/row = 4 x 16B chunks), XOR swizzle.
__device__ __forceinline__ uint32_t swz(uint32_t row, uint32_t c) {
    return row * 64u + ((c ^ ((row >> 1) & 3u)) << 4);
}

// ---------------------------------------------------------------------------
// RoPE table + apply
// ---------------------------------------------------------------------------
__global__ void rope_table_kernel() {
    int l = blockIdx.x;
    int i = threadIdx.x;
    double inv = pow(10000.0, -(2.0 * (double)i) / (double)DH);
    double ph  = (double)l * inv;
    g_cos[l * 32 + i] = (float)cos(ph);
    g_sin[l * 32 + i] = (float)sin(ph);
}

__global__ void rope_apply_kernel(int which) {
    int p = blockIdx.x * blockDim.x + threadIdx.x;
    const int TOTAL = BATCH * NH * SEQ * 32;
    if (p >= TOTAL) return;
    float* T = which ? g_K : g_Q;
    float2* tp = (float2*)T;
    int i = p & 31;
    int l = (p >> 5) & (SEQ - 1);
    float2 v = tp[p];
    float c = g_cos[l * 32 + i];
    float s = g_sin[l * 32 + i];
    float2 r;
    r.x = v.x * c - v.y * s;
    r.y = v.x * s + v.y * c;
    tp[p] = r;
}

// ---------------------------------------------------------------------------
// fp32 [rows][1024] -> expanded bf16 [rows][3072] = [hi | hi | lo]
// ---------------------------------------------------------------------------
__global__ void expand_a_kernel(const float* __restrict__ src,
                                __nv_bfloat16* __restrict__ dst, int n) {
    int i = blockIdx.x * blockDim.x + threadIdx.x;
    if (i >= n) return;
    int row = i >> 10;
    int k   = i & 1023;
    float v = src[i];
    __nv_bfloat16 h = __float2bfloat16(v);
    __nv_bfloat16 l = __float2bfloat16(v - __bfloat162float(h));
    size_t base = (size_t)row * KK + k;
    dst[base]        = h;
    dst[base + 1024] = h;
    dst[base + 2048] = l;
}

__global__ void expand_ga_kernel(int n) {
    int i = blockIdx.x * blockDim.x + threadIdx.x;
    if (i >= n) return;
    int row = i >> 10;
    int k   = i & 1023;
    float v = g_A[i];
    __nv_bfloat16 h = __float2bfloat16(v);
    __nv_bfloat16 l = __float2bfloat16(v - __bfloat162float(h));
    size_t base = (size_t)row * KK + k;
    gap[base]        = h;
    gap[base + 1024] = h;
    gap[base + 2048] = l;
}

// ---------------------------------------------------------------------------
// W [K=1024][N] fp32 -> dst [N][3072] bf16 = [hi | lo | hi]  (B' layout)
// ---------------------------------------------------------------------------
__global__ void transpose_expand_kernel(const float* __restrict__ W,
                                        __nv_bfloat16* __restrict__ dst, int N) {
    __shared__ float tile[32][33];
    int n0 = blockIdx.x * 32;
    int k0 = blockIdx.y * 32;
    int tx = threadIdx.x, ty = threadIdx.y;
#pragma unroll
    for (int i = 0; i < 4; i++)
        tile[ty + i * 8][tx] = W[(size_t)(k0 + ty + i * 8) * N + n0 + tx];
    __syncthreads();
#pragma unroll
    for (int i = 0; i < 4; i++) {
        float v = tile[tx][ty + i * 8];
        __nv_bfloat16 h = __float2bfloat16(v);
        __nv_bfloat16 l = __float2bfloat16(v - __bfloat162float(h));
        size_t off = (size_t)(n0 + ty + i * 8) * KK + k0 + tx;
        dst[off]        = h;
        dst[off + 1024] = l;
        dst[off + 2048] = h;
    }
}

// ---------------------------------------------------------------------------
// Pipelined bf16 mma.sync GEMM: C[8192, N] = A'[8192,3072] @ B'^T[N,3072] + bias
// mode 0: A'=gxp, B'=gwqp (N=3072), scatter g_Q/g_K/g_V
// mode 1: A'=gap, B'=gwpp (N=1024), write Cout
// BM=BN=128, BK=32, 3-stage cp.async, 256 threads = 8 warps (2m x 4n),
// warp tile 64x32, ldmatrix.x4 fragments.
// ---------------------------------------------------------------------------
#define BM 128
#define BN 128
#define BK 32
#define NIT (KK / BK)                 // 96
#define STG 3
#define A_BYTES (BM * BK * 2)         // 8192
#define STG_BYTES (A_BYTES * 2)       // 16384
#define GEMM_SMEM (STG * STG_BYTES)   // 49152

// FIX (R10 bug): stage loader as a real function — the old macro's internal
// loop variable `s` shadowed the caller's `s` in the prologue, so the two
// preloaded stages were each half-garbage (rel_err 0.54).
__device__ __forceinline__ void load_stage(const __nv_bfloat16* __restrict__ A,
                                           const __nv_bfloat16* __restrict__ B,
                                           uint32_t sbase, int buf, int k0,
                                           int m0, int n0, int tid) {
    uint32_t sA = sbase + (uint32_t)buf * STG_BYTES;
    uint32_t sB = sA + A_BYTES;
#pragma unroll
    for (int u = 0; u < 2; u++) {
        int idx = tid + u * 256;
        int row = idx >> 2, c = idx & 3;
        const __nv_bfloat16* ga = A + (size_t)(m0 + row) * KK + k0 + c * 8;
        const __nv_bfloat16* gb = B + (size_t)(n0 + row) * KK + k0 + c * 8;
        CP_ASYNC16(sA + swz(row, c), ga);
        CP_ASYNC16(sB + swz(row, c), gb);
    }
}

__global__ void __launch_bounds__(256)
gemm_mma_kernel(const float* __restrict__ bias, float* __restrict__ Cout,
                int N, int mode) {
    extern __shared__ __align__(16) char smem[];
    uint32_t sbase = smem_u32(smem);

    const __nv_bfloat16* A = mode ? gap : gxp;
    const __nv_bfloat16* B = mode ? gwpp : gwqp;

    int tid = threadIdx.x;
    int warp = tid >> 5, lane = tid & 31;
    int wm = warp >> 2;               // 0..1
    int wn = warp & 3;                // 0..3
    int m0 = blockIdx.y * BM;
    int n0 = blockIdx.x * BN;

    float acc[4][4][4];
#pragma unroll
    for (int mi = 0; mi < 4; mi++)
#pragma unroll
        for (int ni = 0; ni < 4; ni++)
#pragma unroll
            for (int r = 0; r < 4; r++) acc[mi][ni][r] = 0.0f;

#pragma unroll
    for (int pre = 0; pre < STG - 1; pre++) {
        load_stage(A, B, sbase, pre, pre * BK, m0, n0, tid);
        CP_COMMIT();
    }

    for (int it = 0; it < NIT; it++) {
        CP_WAIT1();
        __syncthreads();

        int nxt = it + STG - 1;
        if (nxt < NIT) load_stage(A, B, sbase, nxt % STG, nxt * BK, m0, n0, tid);
        CP_COMMIT();

        uint32_t sA = sbase + (uint32_t)(it % STG) * STG_BYTES;
        uint32_t sB = sA + A_BYTES;

#pragma unroll
        for (int ks = 0; ks < 2; ks++) {
            uint32_t af[4][4];
#pragma unroll
            for (int mi = 0; mi < 4; mi++) {
                uint32_t row = wm * 64 + mi * 16 + (lane & 15);
                uint32_t c = ks * 2 + (lane >> 4);
                ldmx4(af[mi], sA + swz(row, c));
            }
            uint32_t bf[2][4];
#pragma unroll
            for (int np = 0; np < 2; np++) {
                uint32_t row = wn * 32 + np * 16 + (lane & 7) + ((lane >> 4) << 3);
                uint32_t c = ks * 2 + ((lane >> 3) & 1);
                ldmx4(bf[np], sB + swz(row, c));
            }
#pragma unroll
            for (int mi = 0; mi < 4; mi++)
#pragma unroll
                for (int ni = 0; ni < 4; ni++)
                    mma16816(acc[mi][ni], af[mi],
                             bf[ni >> 1][(ni & 1) * 2],
                             bf[ni >> 1][(ni & 1) * 2 + 1]);
        }
    }

    // Epilogue: thread (g=lane>>2, tg=lane&3)
    int g = lane >> 2, tg = lane & 3;
#pragma unroll
    for (int mi = 0; mi < 4; mi++) {
#pragma unroll
        for (int ni = 0; ni < 4; ni++) {
            int col = n0 + wn * 32 + ni * 8 + tg * 2;
            float bx = bias[col];
            float by = bias[col + 1];
#pragma unroll
            for (int half = 0; half < 2; half++) {
                int row = m0 + wm * 64 + mi * 16 + g + half * 8;
                float vx = acc[mi][ni][half * 2 + 0] + bx;
                float vy = acc[mi][ni][half * 2 + 1] + by;
                if (mode == 0) {
                    int b = row >> 11;
                    int l = row & (SEQ - 1);
                    int part = col >> 10;
                    int rem  = col & 1023;
                    int h    = rem >> 6;
                    int d    = rem & 63;
                    float* dst = (part == 0) ? g_Q : (part == 1) ? g_K : g_V;
                    size_t off = ((size_t)((b * NH + h) * SEQ + l)) * DH + d;
                    *(float2*)(dst + off) = make_float2(vx, vy);
                } else {
                    *(float2*)(Cout + (size_t)row * N + col) = make_float2(vx, vy);
                }
            }
        }
    }
}

// ---------------------------------------------------------------------------
// Flash attention (causal + key mask), fp32 — unchanged
// ---------------------------------------------------------------------------
__global__ void __launch_bounds__(128)
flash_attn_kernel(const int* __restrict__ mask) {
    __shared__ float Ks[64][64];
    __shared__ float Vs[64][64];
    __shared__ int   ms[64];

    int bh = blockIdx.y;
    int b  = bh >> 4;
    int h  = bh & 15;
    int qbase = blockIdx.x * 128;
    int t = threadIdx.x;
    int row = qbase + t;

    const float* qptr = g_Q + ((size_t)bh * SEQ + row) * DH;
    float4 q[16];
#pragma unroll
    for (int i = 0; i < 16; i++) q[i] = *(const float4*)(qptr + i * 4);

    float m = -INFINITY;
    float lsum = 0.0f;
    float4 o[16];
#pragma unroll
    for (int i = 0; i < 16; i++) o[i] = make_float4(0.f, 0.f, 0.f, 0.f);

    const float scale = 0.125f;
    int ntiles = blockIdx.x * 2 + 2;

    for (int tile = 0; tile < ntiles; tile++) {
        int kb = tile * 64;
        const float4* kp = (const float4*)(g_K + ((size_t)bh * SEQ + kb) * DH);
        const float4* vp = (const float4*)(g_V + ((size_t)bh * SEQ + kb) * DH);
#pragma unroll
        for (int i = 0; i < 8; i++) {
            ((float4*)Ks)[t + i * 128] = kp[t + i * 128];
            ((float4*)Vs)[t + i * 128] = vp[t + i * 128];
        }
        if (t < 64) ms[t] = mask[b * SEQ + kb + t];
        __syncthreads();

        int kmax = row - kb + 1;
        if (kmax > 64) kmax = 64;
        for (int kk = 0; kk < kmax; kk++) {
            if (!ms[kk]) continue;
            const float4* kr = (const float4*)&Ks[kk][0];
            float s0 = 0.f, s1 = 0.f, s2 = 0.f, s3 = 0.f;
#pragma unroll
            for (int i = 0; i < 16; i++) {
                float4 kv = kr[i];
                float4 qv = q[i];
                s0 += qv.x * kv.x;
                s1 += qv.y * kv.y;
                s2 += qv.z * kv.z;
                s3 += qv.w * kv.w;
            }
            float s = ((s0 + s1) + (s2 + s3)) * scale;
            if (s > m) {
                float c = __expf(m - s);
                lsum *= c;
#pragma unroll
                for (int i = 0; i < 16; i++) {
                    o[i].x *= c; o[i].y *= c; o[i].z *= c; o[i].w *= c;
                }
                m = s;
            }
            float p = __expf(s - m);
            lsum += p;
            const float4* vr = (const float4*)&Vs[kk][0];
#pragma unroll
            for (int i = 0; i < 16; i++) {
                float4 vv = vr[i];
                o[i].x += p * vv.x;
                o[i].y += p * vv.y;
                o[i].z += p * vv.z;
                o[i].w += p * vv.w;
            }
        }
        __syncthreads();
    }

    float inv = (lsum > 0.f) ? (1.0f / lsum) : 0.f;
    float* op = g_A + ((size_t)(b * SEQ + row)) * DMODEL + h * DH;
#pragma unroll
    for (int i = 0; i < 16; i++) {
        float4 v;
        v.x = o[i].x * inv; v.y = o[i].y * inv;
        v.z = o[i].z * inv; v.w = o[i].w * inv;
        *(float4*)(op + i * 4) = v;
    }
}

// ---------------------------------------------------------------------------
// Launch
// ---------------------------------------------------------------------------
extern "C" void kernel_launch(void* const* d_in, const int* in_sizes, int n_in,
                              void* d_out, int out_size) {
    const float* x      = (const float*)d_in[0];
    const float* W_qkv  = (const float*)d_in[1];
    const float* b_qkv  = (const float*)d_in[2];
    const float* W_proj = (const float*)d_in[3];
    const float* b_proj = (const float*)d_in[4];
    const int*   amask  = (const int*)d_in[5];
    float* out = (float*)d_out;

    cudaFuncSetAttribute(gemm_mma_kernel,
                         cudaFuncAttributeMaxDynamicSharedMemorySize, GEMM_SMEM);

    // 1. RoPE tables
    rope_table_kernel<<<SEQ, 32>>>();

    // 2. Operand expansion
    {
        void* p;
        cudaGetSymbolAddress(&p, gxp);
        int n = M_ROWS * DMODEL;
        expand_a_kernel<<<(n + 255) / 256, 256>>>(x, (__nv_bfloat16*)p, n);
    }
    {
        void* p;
        cudaGetSymbolAddress(&p, gwqp);
        dim3 grid(QKV_N / 32, DMODEL / 32);
        transpose_expand_kernel<<<grid, dim3(32, 8)>>>(W_qkv, (__nv_bfloat16*)p, QKV_N);
    }
    {
        void* p;
        cudaGetSymbolAddress(&p, gwpp);
        dim3 grid(DMODEL / 32, DMODEL / 32);
        transpose_expand_kernel<<<grid, dim3(32, 8)>>>(W_proj, (__nv_bfloat16*)p, DMODEL);
    }

    // 3. QKV GEMM (mma.sync, pipelined) + scatter
    {
        dim3 grid(QKV_N / 128, M_ROWS / 128);   // 24 x 64
        gemm_mma_kernel<<<grid, 256, GEMM_SMEM>>>(b_qkv, nullptr, QKV_N, 0);
    }

    // 4. RoPE on Q and K
    {
        int total = BATCH * NH * SEQ * 32;
        int blocks = (total + 255) / 256;
        rope_apply_kernel<<<blocks, 256>>>(0);
        rope_apply_kernel<<<blocks, 256>>>(1);
    }

    // 5. Flash attention
    {
        dim3 grid(SEQ / 128, BATCH * NH);       // 16 x 64
        flash_attn_kernel<<<grid, 128>>>(amask);
    }

    // 6. Expand attention output, projection GEMM
    {
        int n = M_ROWS * DMODEL;
        expand_ga_kernel<<<(n + 255) / 256, 256>>>(n);
        dim3 grid(DMODEL / 128, M_ROWS / 128);  // 8 x 64
        gemm_mma_kernel<<<grid, 256, GEMM_SMEM>>>(b_proj, out, DMODEL, 1);
    }
}

// round 15
// speedup vs baseline: 3.9625x; 2.2878x over previous
#include <cuda_runtime.h>
#include <cuda_bf16.h>
#include <cuda_fp16.h>
#include <math.h>
#include <stdint.h>

// Problem constants
#define BATCH 4
#define SEQ   2048
#define NH    16
#define DH    64
#define DMODEL 1024
#define M_ROWS (BATCH * SEQ)          // 8192
#define QKV_N  (3 * DMODEL)           // 3072
#define KK     3072                   // expanded K' = 3 * DMODEL (bf16x3 fold)

// Scratch (device globals; allocations are forbidden)
__device__ float g_Q[BATCH * NH * SEQ * DH];
__device__ float g_K[BATCH * NH * SEQ * DH];
__device__ float g_V[BATCH * NH * SEQ * DH];
__device__ float g_A[M_ROWS * DMODEL];
__device__ float g_cos[SEQ * (DH / 2)];
__device__ float g_sin[SEQ * (DH / 2)];

// Expanded bf16 operands for dense GEMMs (bf16x3 fold, proven 1.4e-5)
__device__ __nv_bfloat16 gxp[M_ROWS * KK];
__device__ __nv_bfloat16 gap[M_ROWS * KK];
__device__ __nv_bfloat16 gwqp[QKV_N * KK];
__device__ __nv_bfloat16 gwpp[DMODEL * KK];

// fp16 operands for tensor-core flash attention
__device__ __half gQh[BATCH * NH * SEQ * DH];   // [bh][l][d], scaled by 0.125*log2e
__device__ __half gKh[BATCH * NH * SEQ * DH];   // [bh][l][d]
__device__ __half gVth[BATCH * NH * DH * SEQ];  // [bh][d][key]  V^T hi
__device__ __half gVtl[BATCH * NH * DH * SEQ];  // [bh][d][key]  V^T lo

// ---------------------------------------------------------------------------
// helpers
// ---------------------------------------------------------------------------
__device__ __forceinline__ uint32_t smem_u32(const void* p) {
    uint32_t a;
    asm("{ .reg .u64 t; cvta.to.shared.u64 t, %1; cvt.u32.u64 %0, t; }"
        : "=r"(a) : "l"(p));
    return a;
}

__device__ __forceinline__ void mma16816(float* c, const uint32_t* a,
                                         uint32_t b0, uint32_t b1) {
    asm volatile(
        "mma.sync.aligned.m16n8k16.row.col.f32.bf16.bf16.f32 "
        "{%0,%1,%2,%3}, {%4,%5,%6,%7}, {%8,%9}, {%0,%1,%2,%3};"
        : "+f"(c[0]), "+f"(c[1]), "+f"(c[2]), "+f"(c[3])
        : "r"(a[0]), "r"(a[1]), "r"(a[2]), "r"(a[3]), "r"(b0), "r"(b1));
}

__device__ __forceinline__ void mma16816h(float* c, const uint32_t* a,
                                          uint32_t b0, uint32_t b1) {
    asm volatile(
        "mma.sync.aligned.m16n8k16.row.col.f32.f16.f16.f32 "
        "{%0,%1,%2,%3}, {%4,%5,%6,%7}, {%8,%9}, {%0,%1,%2,%3};"
        : "+f"(c[0]), "+f"(c[1]), "+f"(c[2]), "+f"(c[3])
        : "r"(a[0]), "r"(a[1]), "r"(a[2]), "r"(a[3]), "r"(b0), "r"(b1));
}

__device__ __forceinline__ void ldmx4(uint32_t* r, uint32_t addr) {
    asm volatile(
        "ldmatrix.sync.aligned.m8n8.x4.shared.b16 {%0,%1,%2,%3}, [%4];"
        : "=r"(r[0]), "=r"(r[1]), "=r"(r[2]), "=r"(r[3]) : "r"(addr));
}

#define CP_ASYNC16(dst, src) \
    asm volatile("cp.async.cg.shared.global [%0], [%1], 16;" \
                 :: "r"(dst), "l"(src) : "memory")
#define CP_ASYNC4(dst, src) \
    asm volatile("cp.async.ca.shared.global [%0], [%1], 4;" \
                 :: "r"(dst), "l"(src) : "memory")
#define CP_COMMIT() asm volatile("cp.async.commit_group;" ::: "memory")
#define CP_WAIT1()  asm volatile("cp.async.wait_group 1;" ::: "memory")

// GEMM smem tile: 128 rows x 32 bf16 (64B/row = 4 chunks), XOR swizzle
__device__ __forceinline__ uint32_t swz(uint32_t row, uint32_t c) {
    return row * 64u + ((c ^ ((row >> 1) & 3u)) << 4);
}

// Flash smem tile: rows of 64 fp16 (128B/row = 8 chunks), XOR swizzle
__device__ __forceinline__ uint32_t swzQ(uint32_t row, uint32_t c) {
    return row * 128u + ((c ^ (row & 7u)) << 4);
}

// FMA-only exp2 (degree-6 Taylor, err ~8e-6 rel); input clamped at -126.
__device__ __forceinline__ float ex2(float z) {
    z = fmaxf(z, -126.0f);
    float zf = floorf(z);
    float f = z - zf;
    float p = 1.5403530393e-4f;
    p = fmaf(p, f, 1.3333558146e-3f);
    p = fmaf(p, f, 9.6181291076e-3f);
    p = fmaf(p, f, 5.5504108665e-2f);
    p = fmaf(p, f, 2.4022650696e-1f);
    p = fmaf(p, f, 6.9314718056e-1f);
    p = fmaf(p, f, 1.0f);
    return p * __int_as_float(((int)zf + 127) << 23);
}

// ---------------------------------------------------------------------------
// RoPE table
// ---------------------------------------------------------------------------
__global__ void rope_table_kernel() {
    int l = blockIdx.x;
    int i = threadIdx.x;
    double inv = pow(10000.0, -(2.0 * (double)i) / (double)DH);
    double ph  = (double)l * inv;
    g_cos[l * 32 + i] = (float)cos(ph);
    g_sin[l * 32 + i] = (float)sin(ph);
}

// RoPE apply + fp32->fp16 convert.  which=0: g_Q -> gQh (scaled by 0.125*log2e)
//                                   which=1: g_K -> gKh
__global__ void rope_fp16_kernel(int which) {
    int p = blockIdx.x * blockDim.x + threadIdx.x;
    const int TOTAL = BATCH * NH * SEQ * 32;
    if (p >= TOTAL) return;
    const float2* tp = (const float2*)(which ? g_K : g_Q);
    int i = p & 31;
    int l = (p >> 5) & (SEQ - 1);
    float2 v = tp[p];
    float c = g_cos[l * 32 + i];
    float s = g_sin[l * 32 + i];
    float rx = v.x * c - v.y * s;
    float ry = v.x * s + v.y * c;
    if (which == 0) {
        const float SC = 0.18033688011112042f;   // 0.125 * log2(e)
        rx *= SC; ry *= SC;
        ((__half2*)gQh)[p] = __floats2half2_rn(rx, ry);
    } else {
        ((__half2*)gKh)[p] = __floats2half2_rn(rx, ry);
    }
}

// V [bh][key][d] fp32 -> V^T hi/lo fp16 [bh][d][key]
__global__ void vt_kernel() {
    __shared__ float t[32][33];
    int bh = blockIdx.z;
    int kb = blockIdx.x * 32;     // key tile
    int db = blockIdx.y * 32;     // d tile
    int tx = threadIdx.x, ty = threadIdx.y;
    const float* V = g_V + (size_t)bh * SEQ * DH;
#pragma unroll
    for (int i = 0; i < 4; i++)
        t[ty + i * 8][tx] = V[(size_t)(kb + ty + i * 8) * DH + db + tx];
    __syncthreads();
#pragma unroll
    for (int i = 0; i < 4; i++) {
        float v = t[tx][ty + i * 8];
        __half h = __float2half(v);
        __half l = __float2half(v - __half2float(h));
        size_t off = (size_t)bh * DH * SEQ + (size_t)(db + ty + i * 8) * SEQ + kb + tx;
        gVth[off] = h;
        gVtl[off] = l;
    }
}

// ---------------------------------------------------------------------------
// fp32 -> expanded bf16 [hi | hi | lo]
// ---------------------------------------------------------------------------
__global__ void expand_a_kernel(const float* __restrict__ src,
                                __nv_bfloat16* __restrict__ dst, int n) {
    int i = blockIdx.x * blockDim.x + threadIdx.x;
    if (i >= n) return;
    int row = i >> 10;
    int k   = i & 1023;
    float v = src[i];
    __nv_bfloat16 h = __float2bfloat16(v);
    __nv_bfloat16 l = __float2bfloat16(v - __bfloat162float(h));
    size_t base = (size_t)row * KK + k;
    dst[base]        = h;
    dst[base + 1024] = h;
    dst[base + 2048] = l;
}

__global__ void expand_ga_kernel(int n) {
    int i = blockIdx.x * blockDim.x + threadIdx.x;
    if (i >= n) return;
    int row = i >> 10;
    int k   = i & 1023;
    float v = g_A[i];
    __nv_bfloat16 h = __float2bfloat16(v);
    __nv_bfloat16 l = __float2bfloat16(v - __bfloat162float(h));
    size_t base = (size_t)row * KK + k;
    gap[base]        = h;
    gap[base + 1024] = h;
    gap[base + 2048] = l;
}

__global__ void transpose_expand_kernel(const float* __restrict__ W,
                                        __nv_bfloat16* __restrict__ dst, int N) {
    __shared__ float tile[32][33];
    int n0 = blockIdx.x * 32;
    int k0 = blockIdx.y * 32;
    int tx = threadIdx.x, ty = threadIdx.y;
#pragma unroll
    for (int i = 0; i < 4; i++)
        tile[ty + i * 8][tx] = W[(size_t)(k0 + ty + i * 8) * N + n0 + tx];
    __syncthreads();
#pragma unroll
    for (int i = 0; i < 4; i++) {
        float v = tile[tx][ty + i * 8];
        __nv_bfloat16 h = __float2bfloat16(v);
        __nv_bfloat16 l = __float2bfloat16(v - __bfloat162float(h));
        size_t off = (size_t)(n0 + ty + i * 8) * KK + k0 + tx;
        dst[off]        = h;
        dst[off + 1024] = l;
        dst[off + 2048] = h;
    }
}

// ---------------------------------------------------------------------------
// Pipelined bf16 mma.sync GEMM (unchanged from R11 — WIN)
// ---------------------------------------------------------------------------
#define BM 128
#define BN 128
#define BK 32
#define NIT (KK / BK)
#define STG 3
#define A_BYTES (BM * BK * 2)
#define STG_BYTES (A_BYTES * 2)
#define GEMM_SMEM (STG * STG_BYTES)

__device__ __forceinline__ void load_stage(const __nv_bfloat16* __restrict__ A,
                                           const __nv_bfloat16* __restrict__ B,
                                           uint32_t sbase, int buf, int k0,
                                           int m0, int n0, int tid) {
    uint32_t sA = sbase + (uint32_t)buf * STG_BYTES;
    uint32_t sB = sA + A_BYTES;
#pragma unroll
    for (int u = 0; u < 2; u++) {
        int idx = tid + u * 256;
        int row = idx >> 2, c = idx & 3;
        const __nv_bfloat16* ga = A + (size_t)(m0 + row) * KK + k0 + c * 8;
        const __nv_bfloat16* gb = B + (size_t)(n0 + row) * KK + k0 + c * 8;
        CP_ASYNC16(sA + swz(row, c), ga);
        CP_ASYNC16(sB + swz(row, c), gb);
    }
}

__global__ void __launch_bounds__(256)
gemm_mma_kernel(const float* __restrict__ bias, float* __restrict__ Cout,
                int N, int mode) {
    extern __shared__ __align__(16) char smem[];
    uint32_t sbase = smem_u32(smem);

    const __nv_bfloat16* A = mode ? gap : gxp;
    const __nv_bfloat16* B = mode ? gwpp : gwqp;

    int tid = threadIdx.x;
    int warp = tid >> 5, lane = tid & 31;
    int wm = warp >> 2;
    int wn = warp & 3;
    int m0 = blockIdx.y * BM;
    int n0 = blockIdx.x * BN;

    float acc[4][4][4];
#pragma unroll
    for (int mi = 0; mi < 4; mi++)
#pragma unroll
        for (int ni = 0; ni < 4; ni++)
#pragma unroll
            for (int r = 0; r < 4; r++) acc[mi][ni][r] = 0.0f;

#pragma unroll
    for (int pre = 0; pre < STG - 1; pre++) {
        load_stage(A, B, sbase, pre, pre * BK, m0, n0, tid);
        CP_COMMIT();
    }

    for (int it = 0; it < NIT; it++) {
        CP_WAIT1();
        __syncthreads();

        int nxt = it + STG - 1;
        if (nxt < NIT) load_stage(A, B, sbase, nxt % STG, nxt * BK, m0, n0, tid);
        CP_COMMIT();

        uint32_t sA = sbase + (uint32_t)(it % STG) * STG_BYTES;
        uint32_t sB = sA + A_BYTES;

#pragma unroll
        for (int ks = 0; ks < 2; ks++) {
            uint32_t af[4][4];
#pragma unroll
            for (int mi = 0; mi < 4; mi++) {
                uint32_t row = wm * 64 + mi * 16 + (lane & 15);
                uint32_t c = ks * 2 + (lane >> 4);
                ldmx4(af[mi], sA + swz(row, c));
            }
            uint32_t bf[2][4];
#pragma unroll
            for (int np = 0; np < 2; np++) {
                uint32_t row = wn * 32 + np * 16 + (lane & 7) + ((lane >> 4) << 3);
                uint32_t c = ks * 2 + ((lane >> 3) & 1);
                ldmx4(bf[np], sB + swz(row, c));
            }
#pragma unroll
            for (int mi = 0; mi < 4; mi++)
#pragma unroll
                for (int ni = 0; ni < 4; ni++)
                    mma16816(acc[mi][ni], af[mi],
                             bf[ni >> 1][(ni & 1) * 2],
                             bf[ni >> 1][(ni & 1) * 2 + 1]);
        }
    }

    int g = lane >> 2, tg = lane & 3;
#pragma unroll
    for (int mi = 0; mi < 4; mi++) {
#pragma unroll
        for (int ni = 0; ni < 4; ni++) {
            int col = n0 + wn * 32 + ni * 8 + tg * 2;
            float bx = bias[col];
            float by = bias[col + 1];
#pragma unroll
            for (int half = 0; half < 2; half++) {
                int row = m0 + wm * 64 + mi * 16 + g + half * 8;
                float vx = acc[mi][ni][half * 2 + 0] + bx;
                float vy = acc[mi][ni][half * 2 + 1] + by;
                if (mode == 0) {
                    int b = row >> 11;
                    int l = row & (SEQ - 1);
                    int part = col >> 10;
                    int rem  = col & 1023;
                    int h    = rem >> 6;
                    int d    = rem & 63;
                    float* dst = (part == 0) ? g_Q : (part == 1) ? g_K : g_V;
                    size_t off = ((size_t)((b * NH + h) * SEQ + l)) * DH + d;
                    *(float2*)(dst + off) = make_float2(vx, vy);
                } else {
                    *(float2*)(Cout + (size_t)row * N + col) = make_float2(vx, vy);
                }
            }
        }
    }
}

// ---------------------------------------------------------------------------
// Tensor-core flash attention (fp16 HMMA + FMA exp2)
// Grid: (SEQ/128, BH). 256 threads = 8 warps, warp w owns rows w*16..w*16+15.
// Key tiles of 64; 3-stage cp.async (K, V^T hi, V^T lo, mask).
// Scores arrive pre-scaled in log2 domain (0.125*log2e folded into Q).
// ---------------------------------------------------------------------------
#define KV_STG 24576                          // K 8KB + Vh 8KB + Vl 8KB
#define FL_MS  (16384 + 3 * KV_STG)           // mask region offset = 90112
#define FLASH_SMEM (FL_MS + 3 * 256)          // 90880

__device__ __forceinline__ void load_kv(uint32_t sbase,
                                        const __half* __restrict__ Kg,
                                        const __half* __restrict__ Vhg,
                                        const __half* __restrict__ Vlg,
                                        const int* __restrict__ maskrow,
                                        int buf, int kb, int tid) {
    uint32_t sK = sbase + 16384 + (uint32_t)buf * KV_STG;
    uint32_t sVh = sK + 8192;
    uint32_t sVl = sK + 16384;
#pragma unroll
    for (int u = 0; u < 2; u++) {
        int idx = tid + u * 256;
        int row = idx >> 3, c = idx & 7;
        CP_ASYNC16(sK + swzQ(row, c), Kg + (size_t)(kb + row) * DH + c * 8);
        CP_ASYNC16(sVh + swzQ(row, c), Vhg + (size_t)row * SEQ + kb + c * 8);
        CP_ASYNC16(sVl + swzQ(row, c), Vlg + (size_t)row * SEQ + kb + c * 8);
    }
    if (tid < 64)
        CP_ASYNC4(sbase + FL_MS + (uint32_t)buf * 256 + tid * 4, maskrow + kb + tid);
}

__global__ void __launch_bounds__(256, 2)
flash_mma_kernel(const int* __restrict__ mask) {
    extern __shared__ __align__(16) char fsm[];
    uint32_t sbase = smem_u32(fsm);
    uint32_t QS = sbase;

    int bh = blockIdx.y;
    int b = bh >> 4, h = bh & 15;
    int qbase = blockIdx.x * 128;
    int tid = threadIdx.x;
    int warp = tid >> 5, lane = tid & 31;
    int g = lane >> 2, tg = lane & 3;
    int ntiles = blockIdx.x * 2 + 2;

    const __half* Qg  = gQh  + (size_t)bh * SEQ * DH;
    const __half* Kg  = gKh  + (size_t)bh * SEQ * DH;
    const __half* Vhg = gVth + (size_t)bh * DH * SEQ;
    const __half* Vlg = gVtl + (size_t)bh * DH * SEQ;
    const int* maskrow = mask + b * SEQ;

    // prologue: Q (1024 chunks) + stage0 -> group0; stage1 -> group1
#pragma unroll
    for (int u = 0; u < 4; u++) {
        int idx = tid + u * 256;
        int row = idx >> 3, c = idx & 7;
        CP_ASYNC16(QS + swzQ(row, c), Qg + (size_t)(qbase + row) * DH + c * 8);
    }
    load_kv(sbase, Kg, Vhg, Vlg, maskrow, 0, 0, tid);
    CP_COMMIT();
    load_kv(sbase, Kg, Vhg, Vlg, maskrow, 1, 64, tid);
    CP_COMMIT();

    float m0 = -1e30f, m1 = -1e30f, l0 = 0.0f, l1 = 0.0f;
    float o[8][4];
#pragma unroll
    for (int nt = 0; nt < 8; nt++)
#pragma unroll
        for (int r = 0; r < 4; r++) o[nt][r] = 0.0f;

    uint32_t qf[4][4];
    int row0 = qbase + warp * 16 + g;
    int row1 = row0 + 8;

    for (int it = 0; it < ntiles; it++) {
        CP_WAIT1();
        __syncthreads();

        if (it + 2 < ntiles)
            load_kv(sbase, Kg, Vhg, Vlg, maskrow, (it + 2) % 3, (it + 2) * 64, tid);
        CP_COMMIT();

        if (it == 0) {
#pragma unroll
            for (int ks = 0; ks < 4; ks++) {
                uint32_t row = warp * 16 + (lane & 15);
                uint32_t c = ks * 2 + (lane >> 4);
                ldmx4(qf[ks], QS + swzQ(row, c));
            }
        }

        uint32_t sK = sbase + 16384 + (uint32_t)(it % 3) * KV_STG;
        uint32_t sVh = sK + 8192;
        uint32_t sVl = sK + 16384;
        int kb = it * 64;

        // S = Q K^T  (m16 x n64, log2 domain)
        float sacc[8][4];
#pragma unroll
        for (int nt = 0; nt < 8; nt++)
#pragma unroll
            for (int r = 0; r < 4; r++) sacc[nt][r] = 0.0f;

#pragma unroll
        for (int ks = 0; ks < 4; ks++) {
#pragma unroll
            for (int np = 0; np < 4; np++) {
                uint32_t bfr[4];
                uint32_t row = np * 16 + (lane & 7) + ((lane >> 4) << 3);
                uint32_t c = ks * 2 + ((lane >> 3) & 1);
                ldmx4(bfr, sK + swzQ(row, c));
                mma16816h(sacc[2 * np],     qf[ks], bfr[0], bfr[1]);
                mma16816h(sacc[2 * np + 1], qf[ks], bfr[2], bfr[3]);
            }
        }

        // mask + online softmax
        const int* msp = (const int*)(fsm + FL_MS + (it % 3) * 256);
        float tm0 = -1e30f, tm1 = -1e30f;
#pragma unroll
        for (int nt = 0; nt < 8; nt++) {
            int col0 = kb + nt * 8 + tg * 2;
            int col1 = col0 + 1;
            bool k0 = msp[nt * 8 + tg * 2] != 0;
            bool k1 = msp[nt * 8 + tg * 2 + 1] != 0;
            if (!(k0 && col0 <= row0)) sacc[nt][0] = -1e30f;
            if (!(k1 && col1 <= row0)) sacc[nt][1] = -1e30f;
            if (!(k0 && col0 <= row1)) sacc[nt][2] = -1e30f;
            if (!(k1 && col1 <= row1)) sacc[nt][3] = -1e30f;
            tm0 = fmaxf(tm0, fmaxf(sacc[nt][0], sacc[nt][1]));
            tm1 = fmaxf(tm1, fmaxf(sacc[nt][2], sacc[nt][3]));
        }
        tm0 = fmaxf(tm0, __shfl_xor_sync(0xffffffffu, tm0, 1));
        tm0 = fmaxf(tm0, __shfl_xor_sync(0xffffffffu, tm0, 2));
        tm1 = fmaxf(tm1, __shfl_xor_sync(0xffffffffu, tm1, 1));
        tm1 = fmaxf(tm1, __shfl_xor_sync(0xffffffffu, tm1, 2));

        float mn0 = fmaxf(m0, tm0);
        float mn1 = fmaxf(m1, tm1);
        float sc0 = ex2(m0 - mn0);
        float sc1 = ex2(m1 - mn1);
        m0 = mn0; m1 = mn1;
        l0 *= sc0; l1 *= sc1;

        uint32_t pa2[8], pb2[8];
#pragma unroll
        for (int nt = 0; nt < 8; nt++) {
            float p0 = ex2(sacc[nt][0] - m0);
            float p1 = ex2(sacc[nt][1] - m0);
            float p2 = ex2(sacc[nt][2] - m1);
            float p3 = ex2(sacc[nt][3] - m1);
            l0 += p0 + p1;
            l1 += p2 + p3;
            __half2 ha = __floats2half2_rn(p0, p1);
            __half2 hb = __floats2half2_rn(p2, p3);
            pa2[nt] = *(uint32_t*)&ha;
            pb2[nt] = *(uint32_t*)&hb;
            o[nt][0] *= sc0; o[nt][1] *= sc0;
            o[nt][2] *= sc1; o[nt][3] *= sc1;
        }

        // O += P * (Vh + Vl)
#pragma unroll
        for (int kk = 0; kk < 4; kk++) {
            uint32_t pa[4] = { pa2[2 * kk], pb2[2 * kk],
                               pa2[2 * kk + 1], pb2[2 * kk + 1] };
#pragma unroll
            for (int np = 0; np < 4; np++) {
                uint32_t vfr[4];
                uint32_t row = np * 16 + (lane & 7) + ((lane >> 4) << 3);
                uint32_t c = kk * 2 + ((lane >> 3) & 1);
                ldmx4(vfr, sVh + swzQ(row, c));
                mma16816h(o[2 * np],     pa, vfr[0], vfr[1]);
                mma16816h(o[2 * np + 1], pa, vfr[2], vfr[3]);
                ldmx4(vfr, sVl + swzQ(row, c));
                mma16816h(o[2 * np],     pa, vfr[0], vfr[1]);
                mma16816h(o[2 * np + 1], pa, vfr[2], vfr[3]);
            }
        }
    }

    // finalize
    l0 += __shfl_xor_sync(0xffffffffu, l0, 1);
    l0 += __shfl_xor_sync(0xffffffffu, l0, 2);
    l1 += __shfl_xor_sync(0xffffffffu, l1, 1);
    l1 += __shfl_xor_sync(0xffffffffu, l1, 2);
    float inv0 = (l0 > 0.0f) ? (1.0f / l0) : 0.0f;
    float inv1 = (l1 > 0.0f) ? (1.0f / l1) : 0.0f;

    float* oA = g_A + ((size_t)(b * SEQ + row0)) * DMODEL + h * DH;
    float* oB = g_A + ((size_t)(b * SEQ + row1)) * DMODEL + h * DH;
#pragma unroll
    for (int nt = 0; nt < 8; nt++) {
        int cc = nt * 8 + tg * 2;
        *(float2*)(oA + cc) = make_float2(o[nt][0] * inv0, o[nt][1] * inv0);
        *(float2*)(oB + cc) = make_float2(o[nt][2] * inv1, o[nt][3] * inv1);
    }
}

// ---------------------------------------------------------------------------
// Launch
// ---------------------------------------------------------------------------
extern "C" void kernel_launch(void* const* d_in, const int* in_sizes, int n_in,
                              void* d_out, int out_size) {
    const float* x      = (const float*)d_in[0];
    const float* W_qkv  = (const float*)d_in[1];
    const float* b_qkv  = (const float*)d_in[2];
    const float* W_proj = (const float*)d_in[3];
    const float* b_proj = (const float*)d_in[4];
    const int*   amask  = (const int*)d_in[5];
    float* out = (float*)d_out;

    cudaFuncSetAttribute(gemm_mma_kernel,
                         cudaFuncAttributeMaxDynamicSharedMemorySize, GEMM_SMEM);
    cudaFuncSetAttribute(flash_mma_kernel,
                         cudaFuncAttributeMaxDynamicSharedMemorySize, FLASH_SMEM);

    // 1. RoPE tables
    rope_table_kernel<<<SEQ, 32>>>();

    // 2. Operand expansion for GEMMs
    {
        void* p;
        cudaGetSymbolAddress(&p, gxp);
        int n = M_ROWS * DMODEL;
        expand_a_kernel<<<(n + 255) / 256, 256>>>(x, (__nv_bfloat16*)p, n);
    }
    {
        void* p;
        cudaGetSymbolAddress(&p, gwqp);
        dim3 grid(QKV_N / 32, DMODEL / 32);
        transpose_expand_kernel<<<grid, dim3(32, 8)>>>(W_qkv, (__nv_bfloat16*)p, QKV_N);
    }
    {
        void* p;
        cudaGetSymbolAddress(&p, gwpp);
        dim3 grid(DMODEL / 32, DMODEL / 32);
        transpose_expand_kernel<<<grid, dim3(32, 8)>>>(W_proj, (__nv_bfloat16*)p, DMODEL);
    }

    // 3. QKV GEMM + scatter
    {
        dim3 grid(QKV_N / 128, M_ROWS / 128);
        gemm_mma_kernel<<<grid, 256, GEMM_SMEM>>>(b_qkv, nullptr, QKV_N, 0);
    }

    // 4. RoPE + fp16 convert (Q, K); V transpose + split
    {
        int total = BATCH * NH * SEQ * 32;
        int blocks = (total + 255) / 256;
        rope_fp16_kernel<<<blocks, 256>>>(0);
        rope_fp16_kernel<<<blocks, 256>>>(1);
        dim3 grid(SEQ / 32, DH / 32, BATCH * NH);
        vt_kernel<<<grid, dim3(32, 8)>>>();
    }

    // 5. Tensor-core flash attention
    {
        dim3 grid(SEQ / 128, BATCH * NH);
        flash_mma_kernel<<<grid, 256, FLASH_SMEM>>>(amask);
    }

    // 6. Expand attention output, projection GEMM
    {
        int n = M_ROWS * DMODEL;
        expand_ga_kernel<<<(n + 255) / 256, 256>>>(n);
        dim3 grid(DMODEL / 128, M_ROWS / 128);
        gemm_mma_kernel<<<grid, 256, GEMM_SMEM>>>(b_proj, out, DMODEL, 1);
    }
}